// round 12
// baseline (speedup 1.0000x reference)
#include <cuda_runtime.h>
#include <cuda_bf16.h>
#include <cstdint>

#define C 32
#define WARPS 8
#define STRIDE 40            // words per staged row (160B): conflict-free half-warp phases
#define ROWS_T 16            // pairs per warp-iteration
#define BUF_WORDS (ROWS_T * STRIDE)       // 640 words = 2.5KB
#define WARP_WORDS (2 * BUF_WORDS)        // double buffer (gather only; no D staging)
#define SMEM_BYTES (WARPS * WARP_WORDS * 4)  // 40KB -> 3 CTAs/SM

// ---------------------------------------------------------------------------
static __device__ __forceinline__ uint32_t smem_u32(const void* p) {
    uint32_t a;
    asm("{ .reg .u64 t; cvta.to.shared.u64 t, %1; cvt.u32.u64 %0, t; }"
        : "=r"(a) : "l"(p));
    return a;
}

// bf16 two-term split of a float2 -> (hi pair packed, lo pair packed)
static __device__ __forceinline__ uint2 split2(float x, float y) {
    __nv_bfloat162 h = __float22bfloat162_rn(make_float2(x, y));
    float hx = __bfloat162float(h.x);
    float hy = __bfloat162float(h.y);
    __nv_bfloat162 l = __float22bfloat162_rn(make_float2(x - hx, y - hy));
    uint2 r;
    r.x = *(uint32_t*)&h;
    r.y = *(uint32_t*)&l;
    return r;
}

static __device__ __forceinline__ void mma_bf16(float* d, const uint32_t* a,
                                                const uint32_t* b) {
    asm volatile(
        "mma.sync.aligned.m16n8k16.row.col.f32.bf16.bf16.f32 "
        "{%0,%1,%2,%3}, {%4,%5,%6,%7}, {%8,%9}, {%0,%1,%2,%3};"
        : "+f"(d[0]), "+f"(d[1]), "+f"(d[2]), "+f"(d[3])
        : "r"(a[0]), "r"(a[1]), "r"(a[2]), "r"(a[3]), "r"(b[0]), "r"(b[1]));
}

// ---------------------------------------------------------------------------
// Kernel 1: initialize output with bias
// ---------------------------------------------------------------------------
__global__ void init_bias_kernel(float* __restrict__ out,
                                 const float* __restrict__ bias, int n4) {
    int idx = blockIdx.x * blockDim.x + threadIdx.x;
    if (idx < n4) {
        const float4* b4 = (const float4*)bias;
        ((float4*)out)[idx] = b4[idx & 7];
    }
}

// ---------------------------------------------------------------------------
// Kernel 2: transposed GEMM — W is the A operand (M=32 couts, permuted rows),
// gathered input rows are the B operand (N=pairs). Lane accumulators hold 4
// consecutive couts per pair -> red.global.add.v4 straight from registers.
// 16-pair tiles + 3 CTAs/SM for latency hiding; cp.async double buffer +
// 2-ahead index prefetch retained.
// ---------------------------------------------------------------------------
__global__ __launch_bounds__(256, 3) void spconv_hmma_kernel(
    const float* __restrict__ in_feature,
    const float* __restrict__ weights,
    const int2* __restrict__ nbmap,
    float* __restrict__ out,
    int P, int blocksPerSeg)
{
    extern __shared__ uint32_t S[];

    const int tid  = threadIdx.x;
    const int wid  = tid >> 5;
    const int lane = tid & 31;
    const int l4   = lane >> 2;   // 0..7
    const int lm4  = lane & 3;    // 0..3
    const int t8   = lane & 7;    // 16B chunk within 128B row
    const int r8   = lane >> 3;   // 0..3

    const int seg = blockIdx.x / blocksPerSeg;
    const int blk = blockIdx.x % blocksPerSeg;

    // ---- register-resident W fragments as MMA A-operand (hi & lo) ----
    // Row->cout permutation: m-tile m, row r<8 -> cout 4r+2m ; row r>=8 -> 4(r-8)+2m+1
    // => lane's couts {4l4..4l4+3} across (m,reg) — consecutive.
    const float* W = weights + seg * C * C;   // W[cin][cout]
    uint32_t Wh[2][2][4], Wl[2][2][4];
    #pragma unroll
    for (int m = 0; m < 2; m++) {
        #pragma unroll
        for (int kc = 0; kc < 2; kc++) {
            #pragma unroll
            for (int r = 0; r < 4; r++) {
                int cout = 4 * l4 + 2 * m + (r & 1);
                int kk   = 2 * lm4 + 16 * kc + ((r >> 1) * 8);
                uint2 s = split2(W[kk * C + cout], W[(kk + 1) * C + cout]);
                Wh[m][kc][r] = s.x;
                Wl[m][kc][r] = s.y;
            }
        }
    }

    // ---- per-warp contiguous pair range ----
    const int segStart = seg * P;
    const int segEnd   = segStart + P;
    const int warpsPerSeg = blocksPerSeg * WARPS;
    const int perWarp  = (P + warpsPerSeg - 1) / warpsPerSeg;
    const int wStart = segStart + (blk * WARPS + wid) * perWarp;
    const int wEnd   = min(wStart + perWarp, segEnd);
    if (wStart >= wEnd) return;   // no block-wide syncs below; safe

    uint32_t* Swarp = S + wid * WARP_WORDS;
    const uint32_t sbase = smem_u32(Swarp);
    const int nIter = (wEnd - wStart + ROWS_T - 1) / ROWS_T;

    // load 16 pair records into lanes 0..15
    auto loadIJ = [&](int pB) -> int2 {
        int pc = min(pB + lane, segEnd - 1);
        return (lane < 16) ? nbmap[pc] : make_int2(0, 0);
    };
    // issue async gather of 16 fp32 rows into buffer bi
    auto gatherIssue = [&](int bi, int2 ij) {
        uint32_t abase = sbase + bi * (BUF_WORDS * 4);
        #pragma unroll
        for (int g = 0; g < 4; g++) {
            int r = 4 * g + r8;
            int x = __shfl_sync(0xffffffffu, ij.x, r);
            const char* src = (const char*)(in_feature + (size_t)x * C) + t8 * 16;
            uint32_t dst = abase + (r * STRIDE + t8 * 4) * 4;
            asm volatile("cp.async.cg.shared.global [%0], [%1], 16;"
                         :: "r"(dst), "l"(src) : "memory");
        }
    };

    // ---- prologue: indices 2 ahead, gather 1 ahead ----
    int2 ij_cur = loadIJ(wStart);
    gatherIssue(0, ij_cur);
    asm volatile("cp.async.commit_group;" ::: "memory");
    int2 ij_next = (nIter > 1) ? loadIJ(wStart + ROWS_T) : ij_cur;

    for (int t = 0; t < nIter; t++) {
        const int pBase = wStart + t * ROWS_T;
        const int vc = min(ROWS_T, wEnd - pBase);
        const int cur = t & 1;

        // issue gather for t+1 (indices already register-resident)
        if (t + 1 < nIter) gatherIssue(cur ^ 1, ij_next);
        asm volatile("cp.async.commit_group;" ::: "memory");

        // issue index load for t+2 (latency hidden across this iteration)
        int2 ij_next2 = (t + 2 < nIter) ? loadIJ(pBase + 2 * ROWS_T) : ij_next;

        asm volatile("cp.async.wait_group 1;" ::: "memory");
        __syncwarp();

        const float* Af = (const float*)(Swarp + cur * BUF_WORDS);

        // ---- per n-tile (8 pairs): B-frag load+split, MMA, direct RED ----
        #pragma unroll
        for (int n = 0; n < 2; n++) {
            // B frag (col-major): col l4 -> pair row 8n+l4; b0: k=2lm4,+1; b1: k+8.
            uint32_t gh[2][2], gl[2][2];
            #pragma unroll
            for (int kc = 0; kc < 2; kc++) {
                const float* rp = Af + (8 * n + l4) * STRIDE + 16 * kc + 2 * lm4;
                float2 q0 = *(const float2*)(rp);
                float2 q1 = *(const float2*)(rp + 8);
                uint2 s;
                s = split2(q0.x, q0.y); gh[kc][0] = s.x; gl[kc][0] = s.y;
                s = split2(q1.x, q1.y); gh[kc][1] = s.x; gl[kc][1] = s.y;
            }

            float d0[4] = {0.f, 0.f, 0.f, 0.f};   // couts 4l4, 4l4+1
            float d1[4] = {0.f, 0.f, 0.f, 0.f};   // couts 4l4+2, 4l4+3
            #pragma unroll
            for (int kc = 0; kc < 2; kc++) {
                mma_bf16(d0, Wh[0][kc], gh[kc]);
                mma_bf16(d0, Wh[0][kc], gl[kc]);
                mma_bf16(d0, Wl[0][kc], gh[kc]);
                mma_bf16(d1, Wh[1][kc], gh[kc]);
                mma_bf16(d1, Wh[1][kc], gl[kc]);
                mma_bf16(d1, Wl[1][kc], gh[kc]);
            }

            // epilogue: D col c=2lm4+par is pair n*8+c; lane holds couts 4l4..+3
            #pragma unroll
            for (int par = 0; par < 2; par++) {
                int p = n * 8 + 2 * lm4 + par;
                int y = __shfl_sync(0xffffffffu, ij_cur.y, p);
                if (p < vc) {
                    float* op = out + (size_t)y * C + 4 * l4;
                    asm volatile("red.global.add.v4.f32 [%0], {%1,%2,%3,%4};"
                                 :: "l"(op),
                                    "f"(d0[par]), "f"(d0[2 + par]),
                                    "f"(d1[par]), "f"(d1[2 + par])
                                 : "memory");
                }
            }
        }

        ij_cur = ij_next;
        ij_next = ij_next2;
    }
}

// ---------------------------------------------------------------------------
// Inputs: 0 in_feature f32 [N_VOX,32], 1 kernel f32 [27,32,32], 2 bias f32[32],
//         3 nbmap i32 [M,2], 4 nbsizes i32 [27]
// ---------------------------------------------------------------------------
extern "C" void kernel_launch(void* const* d_in, const int* in_sizes, int n_in,
                              void* d_out, int out_size) {
    const float* in_feature = (const float*)d_in[0];
    const float* weights    = (const float*)d_in[1];
    const float* bias       = (const float*)d_in[2];
    const int2*  nbmap      = (const int2*)d_in[3];
    float*       out        = (float*)d_out;

    int M  = in_sizes[3] / 2;
    int K3 = in_sizes[1] / (C * C);
    int P  = M / K3;

    int n4 = out_size / 4;
    init_bias_kernel<<<(n4 + 255) / 256, 256>>>(out, bias, n4);

    static int smem_set = 0;
    if (!smem_set) {
        cudaFuncSetAttribute(spconv_hmma_kernel,
                             cudaFuncAttributeMaxDynamicSharedMemorySize,
                             SMEM_BYTES);
        smem_set = 1;
    }

    int blocksPerSeg = 48;
    spconv_hmma_kernel<<<K3 * blocksPerSeg, 256, SMEM_BYTES>>>(
        in_feature, weights, nbmap, out, P, blocksPerSeg);
}

// round 13
// speedup vs baseline: 1.5777x; 1.5777x over previous
#include <cuda_runtime.h>
#include <cuda_fp16.h>
#include <cstdint>

#define C 32
#define WARPS 8
#define STRIDE 40            // words per staged row (160B): LDS.64 at 2-wf floor
#define ROWS_T 32            // pairs per warp-iteration
#define BUF_WORDS (ROWS_T * STRIDE)       // 1280 words = 5KB
#define WARP_WORDS (2 * BUF_WORDS)        // double buffer (gather only)
#define SMEM_BYTES (WARPS * WARP_WORDS * 4)  // 80KB
#define WLO_SCALE 2048.0f
#define WLO_INV  (1.0f / 2048.0f)

// ---------------------------------------------------------------------------
static __device__ __forceinline__ uint32_t smem_u32(const void* p) {
    uint32_t a;
    asm("{ .reg .u64 t; cvta.to.shared.u64 t, %1; cvt.u32.u64 %0, t; }"
        : "=r"(a) : "l"(p));
    return a;
}

static __device__ __forceinline__ uint32_t pack_h2(float x, float y) {
    __half2 h = __floats2half2_rn(x, y);
    return *(uint32_t*)&h;
}

static __device__ __forceinline__ void mma_f16(float* d, const uint32_t* a,
                                               const uint32_t* b) {
    asm volatile(
        "mma.sync.aligned.m16n8k16.row.col.f32.f16.f16.f32 "
        "{%0,%1,%2,%3}, {%4,%5,%6,%7}, {%8,%9}, {%0,%1,%2,%3};"
        : "+f"(d[0]), "+f"(d[1]), "+f"(d[2]), "+f"(d[3])
        : "r"(a[0]), "r"(a[1]), "r"(a[2]), "r"(a[3]), "r"(b[0]), "r"(b[1]));
}

// ---------------------------------------------------------------------------
// Kernel 1: initialize output with bias
// ---------------------------------------------------------------------------
__global__ void init_bias_kernel(float* __restrict__ out,
                                 const float* __restrict__ bias, int n4) {
    int idx = blockIdx.x * blockDim.x + threadIdx.x;
    if (idx < n4) {
        const float4* b4 = (const float4*)bias;
        ((float4*)out)[idx] = b4[idx & 7];
    }
}

// ---------------------------------------------------------------------------
// Kernel 2: transposed GEMM, fp16 with W-side split.
//   W = Wh + Wl (Wl held scaled by 2048 to stay in fp16 normal range).
//   d = (Wh @ a) + (Wls @ a) * (1/2048)  -> near-fp32 W, fp16 A quantization.
// W is the MMA A operand (M=32 couts, permuted rows); gathered rows are the
// B operand (N=pairs). Lane accumulators hold 4 consecutive couts per pair
// -> red.global.add.v4 straight from registers.
// ---------------------------------------------------------------------------
__global__ __launch_bounds__(256, 2) void spconv_hmma_kernel(
    const float* __restrict__ in_feature,
    const float* __restrict__ weights,
    const int2* __restrict__ nbmap,
    float* __restrict__ out,
    int P, int blocksPerSeg)
{
    extern __shared__ uint32_t S[];

    const int tid  = threadIdx.x;
    const int wid  = tid >> 5;
    const int lane = tid & 31;
    const int l4   = lane >> 2;   // 0..7
    const int lm4  = lane & 3;    // 0..3
    const int t8   = lane & 7;    // 16B chunk within 128B row
    const int r8   = lane >> 3;   // 0..3

    const int seg = blockIdx.x / blocksPerSeg;
    const int blk = blockIdx.x % blocksPerSeg;

    // ---- register-resident W fragments (hi & scaled-lo) as MMA A-operand ----
    // Row->cout permutation: m-tile m, row r<8 -> cout 4r+2m ; r>=8 -> 4(r-8)+2m+1
    // => lane's couts {4l4..4l4+3} across (m,reg) — consecutive.
    const float* W = weights + seg * C * C;   // W[cin][cout]
    uint32_t Wh[2][2][4], Wls[2][2][4];
    #pragma unroll
    for (int m = 0; m < 2; m++) {
        #pragma unroll
        for (int kc = 0; kc < 2; kc++) {
            #pragma unroll
            for (int r = 0; r < 4; r++) {
                int cout = 4 * l4 + 2 * m + (r & 1);
                int kk   = 2 * lm4 + 16 * kc + ((r >> 1) * 8);
                float w0 = W[kk * C + cout];
                float w1 = W[(kk + 1) * C + cout];
                __half2 h = __floats2half2_rn(w0, w1);
                float h0 = __low2float(h), h1 = __high2float(h);
                __half2 l = __floats2half2_rn((w0 - h0) * WLO_SCALE,
                                              (w1 - h1) * WLO_SCALE);
                Wh[m][kc][r]  = *(uint32_t*)&h;
                Wls[m][kc][r] = *(uint32_t*)&l;
            }
        }
    }

    // ---- per-warp contiguous pair range ----
    const int segStart = seg * P;
    const int segEnd   = segStart + P;
    const int warpsPerSeg = blocksPerSeg * WARPS;
    const int perWarp  = (P + warpsPerSeg - 1) / warpsPerSeg;
    const int wStart = segStart + (blk * WARPS + wid) * perWarp;
    const int wEnd   = min(wStart + perWarp, segEnd);
    if (wStart >= wEnd) return;   // no block-wide syncs below; safe

    uint32_t* Swarp = S + wid * WARP_WORDS;
    const uint32_t sbase = smem_u32(Swarp);
    const int nIter = (wEnd - wStart + ROWS_T - 1) / ROWS_T;

    auto loadIJ = [&](int pB) -> int2 {
        int pc = min(pB + lane, segEnd - 1);
        return nbmap[pc];
    };
    auto gatherIssue = [&](int bi, int2 ij) {
        uint32_t abase = sbase + bi * (BUF_WORDS * 4);
        #pragma unroll
        for (int g = 0; g < 8; g++) {
            int r = 4 * g + r8;
            int x = __shfl_sync(0xffffffffu, ij.x, r);
            const char* src = (const char*)(in_feature + (size_t)x * C) + t8 * 16;
            uint32_t dst = abase + (r * STRIDE + t8 * 4) * 4;
            asm volatile("cp.async.cg.shared.global [%0], [%1], 16;"
                         :: "r"(dst), "l"(src) : "memory");
        }
    };

    // ---- prologue: indices 2 ahead, gather 1 ahead ----
    int2 ij_cur = loadIJ(wStart);
    gatherIssue(0, ij_cur);
    asm volatile("cp.async.commit_group;" ::: "memory");
    int2 ij_next = (nIter > 1) ? loadIJ(wStart + ROWS_T) : ij_cur;

    for (int t = 0; t < nIter; t++) {
        const int pBase = wStart + t * ROWS_T;
        const int vc = min(ROWS_T, wEnd - pBase);
        const int cur = t & 1;

        if (t + 1 < nIter) gatherIssue(cur ^ 1, ij_next);
        asm volatile("cp.async.commit_group;" ::: "memory");

        int2 ij_next2 = (t + 2 < nIter) ? loadIJ(pBase + 2 * ROWS_T) : ij_next;

        asm volatile("cp.async.wait_group 1;" ::: "memory");
        __syncwarp();

        const float* Af = (const float*)(Swarp + cur * BUF_WORDS);

        // ---- per n-tile (8 pairs): B-frag load+cvt, MMA, direct RED ----
        #pragma unroll
        for (int n = 0; n < 4; n++) {
            // B frag (col-major): col l4 -> pair row 8n+l4; b0: k=2lm4,+1; b1: k+8.
            uint32_t g[2][2];
            #pragma unroll
            for (int kc = 0; kc < 2; kc++) {
                const float* rp = Af + (8 * n + l4) * STRIDE + 16 * kc + 2 * lm4;
                float2 q0 = *(const float2*)(rp);
                float2 q1 = *(const float2*)(rp + 8);
                g[kc][0] = pack_h2(q0.x, q0.y);
                g[kc][1] = pack_h2(q1.x, q1.y);
            }

            float dh0[4] = {0.f, 0.f, 0.f, 0.f};   // hi: couts 4l4, 4l4+1
            float dh1[4] = {0.f, 0.f, 0.f, 0.f};   // hi: couts 4l4+2, 4l4+3
            float dl0[4] = {0.f, 0.f, 0.f, 0.f};   // scaled-lo
            float dl1[4] = {0.f, 0.f, 0.f, 0.f};
            #pragma unroll
            for (int kc = 0; kc < 2; kc++) {
                mma_f16(dh0, Wh[0][kc], g[kc]);
                mma_f16(dh1, Wh[1][kc], g[kc]);
                mma_f16(dl0, Wls[0][kc], g[kc]);
                mma_f16(dl1, Wls[1][kc], g[kc]);
            }

            // epilogue: D col c=2lm4+par is pair n*8+c; lane holds couts 4l4..+3
            #pragma unroll
            for (int par = 0; par < 2; par++) {
                int p = n * 8 + 2 * lm4 + par;
                int y = __shfl_sync(0xffffffffu, ij_cur.y, p);
                float v0 = fmaf(dl0[par],     WLO_INV, dh0[par]);
                float v1 = fmaf(dl0[2 + par], WLO_INV, dh0[2 + par]);
                float v2 = fmaf(dl1[par],     WLO_INV, dh1[par]);
                float v3 = fmaf(dl1[2 + par], WLO_INV, dh1[2 + par]);
                if (p < vc) {
                    float* op = out + (size_t)y * C + 4 * l4;
                    asm volatile("red.global.add.v4.f32 [%0], {%1,%2,%3,%4};"
                                 :: "l"(op), "f"(v0), "f"(v1), "f"(v2), "f"(v3)
                                 : "memory");
                }
            }
        }

        ij_cur = ij_next;
        ij_next = ij_next2;
    }
}

// ---------------------------------------------------------------------------
// Inputs: 0 in_feature f32 [N_VOX,32], 1 kernel f32 [27,32,32], 2 bias f32[32],
//         3 nbmap i32 [M,2], 4 nbsizes i32 [27]
// ---------------------------------------------------------------------------
extern "C" void kernel_launch(void* const* d_in, const int* in_sizes, int n_in,
                              void* d_out, int out_size) {
    const float* in_feature = (const float*)d_in[0];
    const float* weights    = (const float*)d_in[1];
    const float* bias       = (const float*)d_in[2];
    const int2*  nbmap      = (const int2*)d_in[3];
    float*       out        = (float*)d_out;

    int M  = in_sizes[3] / 2;
    int K3 = in_sizes[1] / (C * C);
    int P  = M / K3;

    int n4 = out_size / 4;
    init_bias_kernel<<<(n4 + 255) / 256, 256>>>(out, bias, n4);

    static int smem_set = 0;
    if (!smem_set) {
        cudaFuncSetAttribute(spconv_hmma_kernel,
                             cudaFuncAttributeMaxDynamicSharedMemorySize,
                             SMEM_BYTES);
        smem_set = 1;
    }

    int blocksPerSeg = 32;
    spconv_hmma_kernel<<<K3 * blocksPerSeg, 256, SMEM_BYTES>>>(
        in_feature, weights, nbmap, out, P, blocksPerSeg);
}